// round 6
// baseline (speedup 1.0000x reference)
#include <cuda_runtime.h>
#include <cuda_bf16.h>
#include <cstdint>

#define BATCH 8192
#define DIM   2048
#define EPSV  1e-8f
#define MARGINV 0.2f

static constexpr int THREADS = 256;
static constexpr int ROW_F4  = DIM / 4;        // 512 float4 per row
static constexpr int GRID    = 296;            // 2 blocks/SM * 148 SMs
static constexpr int MAX_K   = (BATCH + GRID - 1) / GRID;   // 28
static constexpr int BUF_F4  = 6 * ROW_F4;     // 3072 float4 per buffer
static constexpr size_t SMEM_BYTES = 2 * BUF_F4 * 16 + MAX_K * 16;

__device__ float2 g_part[GRID];

__device__ __forceinline__ float dot4(float4 a, float4 b) {
    return a.x * b.x + a.y * b.y + a.z * b.z + a.w * b.w;
}

__device__ __forceinline__ void cp16(uint32_t dst, const float4* src) {
    asm volatile("cp.async.cg.shared.global [%0], [%1], 16;" :: "r"(dst), "l"(src));
}
__device__ __forceinline__ void cp_commit() {
    asm volatile("cp.async.commit_group;");
}
template <int N>
__device__ __forceinline__ void cp_wait() {
    asm volatile("cp.async.wait_group %0;" :: "n"(N));
}

__global__ __launch_bounds__(THREADS)
void contrastive_main(const float4* __restrict__ img,
                      const float4* __restrict__ txt,
                      const int2* __restrict__ cand_img,
                      const int2* __restrict__ cand_txt,
                      float* __restrict__ out) {
    extern __shared__ char smem_raw[];
    float4* buf = (float4*)smem_raw;                            // [2][6][512]
    int4* cands = (int4*)(smem_raw + (size_t)2 * BUF_F4 * 16);  // [MAX_K]
    const uint32_t sbase = (uint32_t)__cvta_generic_to_shared(smem_raw);

    const int b = blockIdx.x;
    const int t = threadIdx.x;
    const int K = (BATCH - 1 - b) / GRID + 1;   // 27 or 28 rows for this block

    // Preload all candidate indices for this block's rows (one latency, once).
    if (t < K) {
        const int r = b + t * GRID;
        const int2 va = cand_img[r];
        const int2 vb = cand_txt[r];
        cands[t] = make_int4(va.x & (BATCH - 1), va.y & (BATCH - 1),
                             vb.x & (BATCH - 1), vb.y & (BATCH - 1));
    }
    __syncthreads();

    __shared__ float s[THREADS / 32][11];
    const int lane = t & 31, warp = t >> 5;

    float sum_i2t = 0.f, sum_t2i = 0.f;   // meaningful on t0 only

    // Stage rows for iteration k into buffer slot (12 cp.async per thread).
    auto stage = [&](int k, int slot) {
        const int r = b + k * GRID;
        const int4 c = cands[k];
        const uint32_t sb = sbase + (uint32_t)slot * (BUF_F4 * 16);
        const float4* p0 = img + (size_t)r   * ROW_F4;   // anchor img
        const float4* p1 = txt + (size_t)r   * ROW_F4;   // anchor txt
        const float4* p2 = img + (size_t)c.x * ROW_F4;   // img[a0]
        const float4* p3 = img + (size_t)c.y * ROW_F4;   // img[a1]
        const float4* p4 = txt + (size_t)c.z * ROW_F4;   // txt[b0]
        const float4* p5 = txt + (size_t)c.w * ROW_F4;   // txt[b1]
        cp16(sb + (uint32_t)(0 * ROW_F4 + t)       * 16, p0 + t);
        cp16(sb + (uint32_t)(0 * ROW_F4 + t + 256) * 16, p0 + t + 256);
        cp16(sb + (uint32_t)(1 * ROW_F4 + t)       * 16, p1 + t);
        cp16(sb + (uint32_t)(1 * ROW_F4 + t + 256) * 16, p1 + t + 256);
        cp16(sb + (uint32_t)(2 * ROW_F4 + t)       * 16, p2 + t);
        cp16(sb + (uint32_t)(2 * ROW_F4 + t + 256) * 16, p2 + t + 256);
        cp16(sb + (uint32_t)(3 * ROW_F4 + t)       * 16, p3 + t);
        cp16(sb + (uint32_t)(3 * ROW_F4 + t + 256) * 16, p3 + t + 256);
        cp16(sb + (uint32_t)(4 * ROW_F4 + t)       * 16, p4 + t);
        cp16(sb + (uint32_t)(4 * ROW_F4 + t + 256) * 16, p4 + t + 256);
        cp16(sb + (uint32_t)(5 * ROW_F4 + t)       * 16, p5 + t);
        cp16(sb + (uint32_t)(5 * ROW_F4 + t + 256) * 16, p5 + t + 256);
        cp_commit();
    };

    stage(0, 0);

    for (int k = 0; k < K; k++) {
        const int slot = k & 1;
        if (k + 1 < K) {
            stage(k + 1, slot ^ 1);
            cp_wait<1>();   // group k complete (per-thread; thread reads only its own words)
        } else {
            cp_wait<0>();
        }

        const float4* Bf = buf + slot * BUF_F4;
        const float4 iv0 = Bf[0 * ROW_F4 + t], iv1 = Bf[0 * ROW_F4 + t + 256];
        const float4 tv0 = Bf[1 * ROW_F4 + t], tv1 = Bf[1 * ROW_F4 + t + 256];
        const float4 A00 = Bf[2 * ROW_F4 + t], A01 = Bf[2 * ROW_F4 + t + 256];
        const float4 A10 = Bf[3 * ROW_F4 + t], A11 = Bf[3 * ROW_F4 + t + 256];
        const float4 B00 = Bf[4 * ROW_F4 + t], B01 = Bf[4 * ROW_F4 + t + 256];
        const float4 B10 = Bf[5 * ROW_F4 + t], B11 = Bf[5 * ROW_F4 + t + 256];

        float acc[11];
        acc[0]  = dot4(iv0, iv0) + dot4(iv1, iv1);   // ||img||^2
        acc[1]  = dot4(tv0, tv0) + dot4(tv1, tv1);   // ||text||^2
        acc[2]  = dot4(iv0, tv0) + dot4(iv1, tv1);   // img.text
        acc[3]  = dot4(tv0, A00) + dot4(tv1, A01);   // text . img[a0]
        acc[4]  = dot4(A00, A00) + dot4(A01, A01);   // ||img[a0]||^2
        acc[5]  = dot4(tv0, A10) + dot4(tv1, A11);
        acc[6]  = dot4(A10, A10) + dot4(A11, A11);
        acc[7]  = dot4(iv0, B00) + dot4(iv1, B01);   // img . text[b0]
        acc[8]  = dot4(B00, B00) + dot4(B01, B01);
        acc[9]  = dot4(iv0, B10) + dot4(iv1, B11);
        acc[10] = dot4(B10, B10) + dot4(B11, B11);

        #pragma unroll
        for (int q = 0; q < 11; q++) {
            float v = acc[q];
            #pragma unroll
            for (int off = 16; off > 0; off >>= 1)
                v += __shfl_xor_sync(0xFFFFFFFFu, v, off);
            acc[q] = v;
        }
        if (lane == 0) {
            #pragma unroll
            for (int q = 0; q < 11; q++) s[warp][q] = acc[q];
        }
        __syncthreads();

        if (t == 0) {
            float r[11];
            #pragma unroll
            for (int q = 0; q < 11; q++) {
                float v = 0.f;
                #pragma unroll
                for (int w = 0; w < THREADS / 32; w++) v += s[w][q];
                r[q] = v;
            }

            const float n_i = sqrtf(r[0]);
            const float n_t = sqrtf(r[1]);
            const float prod = n_i * n_t;
            const float pos_dist = 1.0f - r[2] / fmaxf(prod, EPSV);
            const float cosv = r[2] / prod;

            const float dA0 = 1.0f - r[3] / fmaxf(n_t * sqrtf(r[4]), EPSV);
            const float dA1 = 1.0f - r[5] / fmaxf(n_t * sqrtf(r[6]), EPSV);
            const float t2i_neg = (dA1 <= dA0) ? dA1 : dA0;

            const float dB0 = 1.0f - r[7] / fmaxf(n_i * sqrtf(r[8]), EPSV);
            const float dB1 = 1.0f - r[9] / fmaxf(n_i * sqrtf(r[10]), EPSV);
            const float i2t_neg = (dB1 <= dB0) ? dB1 : dB0;

            const float i2t_loss = fmaxf(pos_dist - i2t_neg + MARGINV, 0.0f);
            const float t2i_loss = fmaxf(pos_dist - t2i_neg + MARGINV, 0.0f);

            const int row = b + k * GRID;
            out[1 + row]         = cosv;   // i2t_cosine
            out[1 + BATCH + row] = cosv;   // t2i_cosine (same symmetric formula)
            sum_i2t += i2t_loss;
            sum_t2i += t2i_loss;
        }
        __syncthreads();   // protect s[][] for next iteration
    }

    if (t == 0) g_part[b] = make_float2(sum_i2t, sum_t2i);
}

__global__ __launch_bounds__(512)
void contrastive_reduce(float* __restrict__ out) {
    const int t = threadIdx.x;
    float si = 0.f, st = 0.f;
    if (t < GRID) {
        const float2 v = g_part[t];
        si = v.x; st = v.y;
    }
    #pragma unroll
    for (int off = 16; off > 0; off >>= 1) {
        si += __shfl_xor_sync(0xFFFFFFFFu, si, off);
        st += __shfl_xor_sync(0xFFFFFFFFu, st, off);
    }
    __shared__ float ssi[16], sst[16];
    const int lane = t & 31, warp = t >> 5;
    if (lane == 0) { ssi[warp] = si; sst[warp] = st; }
    __syncthreads();
    if (t == 0) {
        float a = 0.f, bsum = 0.f;
        #pragma unroll
        for (int w = 0; w < 16; w++) { a += ssi[w]; bsum += sst[w]; }
        out[0] = a / (float)BATCH + bsum / (float)BATCH;
    }
}

extern "C" void kernel_launch(void* const* d_in, const int* in_sizes, int n_in,
                              void* d_out, int out_size) {
    const float4* img = (const float4*)d_in[0];
    const float4* txt = (const float4*)d_in[1];
    // d_in[2] = labels (unused), d_in[3] = locations (unused)
    const int2* cand_img = (const int2*)d_in[4];
    const int2* cand_txt = (const int2*)d_in[5];
    float* out = (float*)d_out;

    static bool attr_set = false;
    if (!attr_set) {
        cudaFuncSetAttribute(contrastive_main,
                             cudaFuncAttributeMaxDynamicSharedMemorySize,
                             (int)SMEM_BYTES);
        attr_set = true;
    }

    contrastive_main<<<GRID, THREADS, SMEM_BYTES>>>(img, txt, cand_img, cand_txt, out);
    contrastive_reduce<<<1, 512>>>(out);
}

// round 7
// speedup vs baseline: 1.3913x; 1.3913x over previous
#include <cuda_runtime.h>
#include <cuda_bf16.h>
#include <cstdint>

#define BATCH 8192
#define DIM   2048
#define EPSV  1e-8f
#define MARGINV 0.2f

static constexpr int THREADS = 256;
static constexpr int ROW_F4  = DIM / 4;   // 512

__device__ float2 g_loss[BATCH];

__device__ __forceinline__ float dot4(float4 a, float4 b) {
    return a.x * b.x + a.y * b.y + a.z * b.z + a.w * b.w;
}

__global__ __launch_bounds__(THREADS, 6)
void contrastive_main(const float4* __restrict__ img,
                      const float4* __restrict__ txt,
                      const int2* __restrict__ cand_img,
                      const int2* __restrict__ cand_txt,
                      float* __restrict__ out) {
    const int row = blockIdx.x;
    const int t   = threadIdx.x;

    // cand arrays are int32 (JAX x64-disabled downcast; proven in R1->R2)
    const int2 va = cand_img[row];
    const int2 vb = cand_txt[row];
    const int a0 = va.x & (BATCH - 1), a1 = va.y & (BATCH - 1);
    const int b0 = vb.x & (BATCH - 1), b1 = vb.y & (BATCH - 1);

    const float4* ir = img + (size_t)row * ROW_F4;
    const float4* tr = txt + (size_t)row * ROW_F4;

    float acc[11];

    // ---- Phase 1: anchors + img-candidate gathers (8 loads live) ----
    {
        const float4* gA0 = img + (size_t)a0 * ROW_F4;
        const float4* gA1 = img + (size_t)a1 * ROW_F4;
        const float4 iv0 = ir[t],  iv1 = ir[t + THREADS];
        const float4 tv0 = tr[t],  tv1 = tr[t + THREADS];
        const float4 A00 = gA0[t], A01 = gA0[t + THREADS];
        const float4 A10 = gA1[t], A11 = gA1[t + THREADS];

        acc[0] = dot4(iv0, iv0) + dot4(iv1, iv1);   // ||img||^2
        acc[1] = dot4(tv0, tv0) + dot4(tv1, tv1);   // ||text||^2
        acc[2] = dot4(iv0, tv0) + dot4(iv1, tv1);   // img.text
        acc[3] = dot4(tv0, A00) + dot4(tv1, A01);   // text . img[a0]
        acc[4] = dot4(A00, A00) + dot4(A01, A01);   // ||img[a0]||^2
        acc[5] = dot4(tv0, A10) + dot4(tv1, A11);
        acc[6] = dot4(A10, A10) + dot4(A11, A11);

        // ---- Phase 2: text-candidate gathers (A regs dead, reuse) ----
        const float4* gB0 = txt + (size_t)b0 * ROW_F4;
        const float4* gB1 = txt + (size_t)b1 * ROW_F4;
        const float4 B00 = gB0[t], B01 = gB0[t + THREADS];
        const float4 B10 = gB1[t], B11 = gB1[t + THREADS];

        acc[7]  = dot4(iv0, B00) + dot4(iv1, B01);  // img . text[b0]
        acc[8]  = dot4(B00, B00) + dot4(B01, B01);
        acc[9]  = dot4(iv0, B10) + dot4(iv1, B11);
        acc[10] = dot4(B10, B10) + dot4(B11, B11);
    }

    #pragma unroll
    for (int k = 0; k < 11; k++) {
        float v = acc[k];
        #pragma unroll
        for (int off = 16; off > 0; off >>= 1)
            v += __shfl_xor_sync(0xFFFFFFFFu, v, off);
        acc[k] = v;
    }

    __shared__ float s[THREADS / 32][11];
    const int lane = t & 31, warp = t >> 5;
    if (lane == 0) {
        #pragma unroll
        for (int k = 0; k < 11; k++) s[warp][k] = acc[k];
    }
    __syncthreads();

    if (warp == 0) {
        // lane k (k<11) owns accumulator k: parallel cross-warp sum
        float r = 0.f;
        if (lane < 11) {
            #pragma unroll
            for (int w = 0; w < THREADS / 32; w++) r += s[w][lane];
        }
        // gather all 11 sums to lane 0
        float rr[11];
        #pragma unroll
        for (int k = 0; k < 11; k++)
            rr[k] = __shfl_sync(0xFFFFFFFFu, r, k);

        if (lane == 0) {
            const float n_i = sqrtf(rr[0]);
            const float n_t = sqrtf(rr[1]);
            const float prod = n_i * n_t;
            const float pos_dist = 1.0f - rr[2] / fmaxf(prod, EPSV);
            const float cosv = rr[2] / prod;

            const float dA0 = 1.0f - rr[3] / fmaxf(n_t * sqrtf(rr[4]), EPSV);
            const float dA1 = 1.0f - rr[5] / fmaxf(n_t * sqrtf(rr[6]), EPSV);
            const float t2i_neg = (dA1 <= dA0) ? dA1 : dA0;

            const float dB0 = 1.0f - rr[7] / fmaxf(n_i * sqrtf(rr[8]), EPSV);
            const float dB1 = 1.0f - rr[9] / fmaxf(n_i * sqrtf(rr[10]), EPSV);
            const float i2t_neg = (dB1 <= dB0) ? dB1 : dB0;

            const float i2t_loss = fmaxf(pos_dist - i2t_neg + MARGINV, 0.0f);
            const float t2i_loss = fmaxf(pos_dist - t2i_neg + MARGINV, 0.0f);

            out[1 + row]         = cosv;   // i2t_cosine
            out[1 + BATCH + row] = cosv;   // t2i_cosine (same symmetric formula)
            g_loss[row] = make_float2(i2t_loss, t2i_loss);
        }
    }
}

__global__ __launch_bounds__(1024)
void contrastive_reduce(float* __restrict__ out) {
    const int t = threadIdx.x;
    const float4* lp = (const float4*)g_loss;   // 4096 float4 = 8192 float2
    float si = 0.f, st = 0.f;
    #pragma unroll
    for (int i = t; i < BATCH / 2; i += 1024) {
        float4 v = lp[i];
        si += v.x + v.z;
        st += v.y + v.w;
    }
    #pragma unroll
    for (int off = 16; off > 0; off >>= 1) {
        si += __shfl_xor_sync(0xFFFFFFFFu, si, off);
        st += __shfl_xor_sync(0xFFFFFFFFu, st, off);
    }
    __shared__ float ssi[32], sst[32];
    const int lane = t & 31, warp = t >> 5;
    if (lane == 0) { ssi[warp] = si; sst[warp] = st; }
    __syncthreads();
    if (t == 0) {
        float a = 0.f, b = 0.f;
        #pragma unroll
        for (int w = 0; w < 32; w++) { a += ssi[w]; b += sst[w]; }
        out[0] = a / (float)BATCH + b / (float)BATCH;
    }
}

extern "C" void kernel_launch(void* const* d_in, const int* in_sizes, int n_in,
                              void* d_out, int out_size) {
    const float4* img = (const float4*)d_in[0];
    const float4* txt = (const float4*)d_in[1];
    // d_in[2] = labels (unused), d_in[3] = locations (unused)
    const int2* cand_img = (const int2*)d_in[4];
    const int2* cand_txt = (const int2*)d_in[5];
    float* out = (float*)d_out;

    contrastive_main<<<BATCH, THREADS>>>(img, txt, cand_img, cand_txt, out);
    contrastive_reduce<<<1, 1024>>>(out);
}